// round 2
// baseline (speedup 1.0000x reference)
#include <cuda_runtime.h>
#include <cuda_bf16.h>

#define D   256
#define F   1024
#define NL  4
#define NC  10

// Block-wide sum over 256 threads (8 warps). Returns total to all threads.
__device__ __forceinline__ float blockReduceSum(float v, float* red) {
    #pragma unroll
    for (int o = 16; o > 0; o >>= 1) v += __shfl_xor_sync(0xffffffffu, v, o);
    int wid = threadIdx.x >> 5;
    if ((threadIdx.x & 31) == 0) red[wid] = v;
    __syncthreads();
    if (threadIdx.x < 8) {
        v = red[threadIdx.x];
        #pragma unroll
        for (int o = 4; o > 0; o >>= 1) v += __shfl_xor_sync(0xffu, v, o);
        if (threadIdx.x == 0) red[0] = v;
    }
    __syncthreads();
    float r = red[0];
    __syncthreads();  // red reusable by next reduction
    return r;
}

// JAX default gelu: approximate=True (tanh form)
__device__ __forceinline__ float gelu_tanh(float x) {
    const float c = 0.7978845608028654f;   // sqrt(2/pi)
    float u = c * (x + 0.044715f * x * x * x);
    return 0.5f * x * (1.0f + tanhf(u));
}

__global__ void __launch_bounds__(256)
performer_cls_kernel(const int*   __restrict__ xx,
                     const float* __restrict__ emb_tok,
                     const float* __restrict__ emb_pos,
                     const float* __restrict__ ln1_s,
                     const float* __restrict__ ln1_b,
                     const float* __restrict__ wv,
                     const float* __restrict__ wo,
                     const float* __restrict__ bo,
                     const float* __restrict__ ln2_s,
                     const float* __restrict__ ln2_b,
                     const float* __restrict__ w1,
                     const float* __restrict__ b1,
                     const float* __restrict__ w2,
                     const float* __restrict__ b2,
                     const float* __restrict__ wcls,
                     const float* __restrict__ bcls,
                     float* __restrict__ out,
                     int N)
{
    __shared__ float y[D];     // LN output
    __shared__ float t[F];     // matvec intermediates (v0 / MLP hidden / final h)
    __shared__ float red[8];

    const int tid = threadIdx.x;
    const int b   = blockIdx.x;

    // h0 = emb_tok[x[b,0]] + emb_pos[0]
    const int tok = xx[b * N];
    float hv = emb_tok[tok * D + tid] + emb_pos[tid];

    for (int l = 0; l < NL; ++l) {
        // ---------- LN1 ----------
        float s  = blockReduceSum(hv, red);
        float sq = blockReduceSum(hv * hv, red);
        float mu  = s * (1.0f / D);
        float var = sq * (1.0f / D) - mu * mu;
        float inv = rsqrtf(var + 1e-5f);
        y[tid] = (hv - mu) * inv * ln1_s[l * D + tid] + ln1_b[l * D + tid];
        __syncthreads();

        // ---------- v0 = LN1(h) @ wv[l]  (attention at pos 0 == v0) ----------
        {
            const float* W = wv + l * D * D;
            float acc = 0.0f;
            #pragma unroll 8
            for (int d = 0; d < D; ++d) acc = fmaf(y[d], W[d * D + tid], acc);
            t[tid] = acc;
        }
        __syncthreads();

        // ---------- o = v0 @ wo[l] + bo[l];  h += o ----------
        {
            const float* W = wo + l * D * D;
            float acc = bo[l * D + tid];
            #pragma unroll 8
            for (int d = 0; d < D; ++d) acc = fmaf(t[d], W[d * D + tid], acc);
            hv += acc;
        }
        // (no sync needed: next reductions sync before any shared reuse)

        // ---------- LN2 ----------
        s  = blockReduceSum(hv, red);
        sq = blockReduceSum(hv * hv, red);
        mu  = s * (1.0f / D);
        var = sq * (1.0f / D) - mu * mu;
        inv = rsqrtf(var + 1e-5f);
        y[tid] = (hv - mu) * inv * ln2_s[l * D + tid] + ln2_b[l * D + tid];
        __syncthreads();

        // ---------- hidden = gelu(y @ w1[l] + b1[l])  (4 cols per thread) ----------
        {
            const float* W1 = w1 + l * D * F;
            float a0 = b1[l * F + tid];
            float a1 = b1[l * F + tid + 256];
            float a2 = b1[l * F + tid + 512];
            float a3 = b1[l * F + tid + 768];
            #pragma unroll 4
            for (int d = 0; d < D; ++d) {
                float yd = y[d];
                const float* r = W1 + d * F + tid;
                a0 = fmaf(yd, r[0],   a0);
                a1 = fmaf(yd, r[256], a1);
                a2 = fmaf(yd, r[512], a2);
                a3 = fmaf(yd, r[768], a3);
            }
            t[tid]       = gelu_tanh(a0);
            t[tid + 256] = gelu_tanh(a1);
            t[tid + 512] = gelu_tanh(a2);
            t[tid + 768] = gelu_tanh(a3);
        }
        __syncthreads();

        // ---------- h += hidden @ w2[l] + b2[l] ----------
        {
            const float* W2 = w2 + l * F * D;
            float acc = b2[l * D + tid];
            #pragma unroll 8
            for (int j = 0; j < F; ++j) acc = fmaf(t[j], W2[j * D + tid], acc);
            hv += acc;
        }
        // next LN1 reductions provide the sync before y/t reuse
    }

    // ---------- classifier: out[b] = h0 @ wcls + bcls ----------
    t[tid] = hv;
    __syncthreads();
    if (tid < NC) {
        float acc = bcls[tid];
        #pragma unroll 8
        for (int d = 0; d < D; ++d) acc = fmaf(t[d], wcls[d * NC + tid], acc);
        out[b * NC + tid] = acc;
    }
}

extern "C" void kernel_launch(void* const* d_in, const int* in_sizes, int n_in,
                              void* d_out, int out_size)
{
    // metadata order (setup_inputs dict order):
    //  0: x         (int32,  B*N)
    //  1: emb_tok   (V*D)       2: emb_pos (N*D)
    //  3: proj      (unused)
    //  4: ln1_s     5: ln1_b
    //  6: wq (unused) 7: wk (unused) 8: wv
    //  9: wo        10: bo
    // 11: ln2_s     12: ln2_b
    // 13: w1        14: b1
    // 15: w2        16: b2
    // 17: w_cls     18: b_cls
    const int*   xx      = (const int*)  d_in[0];
    const float* emb_tok = (const float*)d_in[1];
    const float* emb_pos = (const float*)d_in[2];
    const float* ln1_s   = (const float*)d_in[4];
    const float* ln1_b   = (const float*)d_in[5];
    const float* wv      = (const float*)d_in[8];
    const float* wo      = (const float*)d_in[9];
    const float* bo      = (const float*)d_in[10];
    const float* ln2_s   = (const float*)d_in[11];
    const float* ln2_b   = (const float*)d_in[12];
    const float* w1      = (const float*)d_in[13];
    const float* b1      = (const float*)d_in[14];
    const float* w2      = (const float*)d_in[15];
    const float* b2      = (const float*)d_in[16];
    const float* wcls    = (const float*)d_in[17];
    const float* bcls    = (const float*)d_in[18];
    float* out = (float*)d_out;

    const int B = out_size / NC;      // 16
    const int N = in_sizes[0] / B;    // 4096

    performer_cls_kernel<<<B, 256>>>(xx, emb_tok, emb_pos, ln1_s, ln1_b,
                                     wv, wo, bo, ln2_s, ln2_b,
                                     w1, b1, w2, b2, wcls, bcls, out, N);
}

// round 3
// speedup vs baseline: 5.3940x; 5.3940x over previous
#include <cuda_runtime.h>
#include <cuda_bf16.h>

#define D    256
#define F    1024
#define NL   4
#define NC   10
#define T    1024   // threads per block

// Block-wide sum over 1024 threads (32 warps). Returns total to all threads.
__device__ __forceinline__ float blockReduceSum(float v, float* red) {
    #pragma unroll
    for (int o = 16; o > 0; o >>= 1) v += __shfl_xor_sync(0xffffffffu, v, o);
    int wid = threadIdx.x >> 5;
    if ((threadIdx.x & 31) == 0) red[wid] = v;
    __syncthreads();
    if (threadIdx.x < 32) {
        v = red[threadIdx.x];
        #pragma unroll
        for (int o = 16; o > 0; o >>= 1) v += __shfl_xor_sync(0xffffffffu, v, o);
        if (threadIdx.x == 0) red[0] = v;
    }
    __syncthreads();
    float r = red[0];
    __syncthreads();
    return r;
}

// JAX default gelu: approximate=True (tanh form)
__device__ __forceinline__ float gelu_tanh(float x) {
    const float c = 0.7978845608028654f;   // sqrt(2/pi)
    float u = c * (x + 0.044715f * x * x * x);
    return 0.5f * x * (1.0f + tanhf(u));
}

__global__ void __launch_bounds__(T)
performer_cls_kernel(const int*   __restrict__ xx,
                     const float* __restrict__ emb_tok,
                     const float* __restrict__ emb_pos,
                     const float* __restrict__ ln1_s,
                     const float* __restrict__ ln1_b,
                     const float* __restrict__ wv,
                     const float* __restrict__ wo,
                     const float* __restrict__ bo,
                     const float* __restrict__ ln2_s,
                     const float* __restrict__ ln2_b,
                     const float* __restrict__ w1,
                     const float* __restrict__ b1,
                     const float* __restrict__ w2,
                     const float* __restrict__ b2,
                     const float* __restrict__ wcls,
                     const float* __restrict__ bcls,
                     float* __restrict__ out,
                     int N)
{
    __shared__ float sh_vec[F];        // matvec input vector (256 or 1024 live)
    __shared__ float partial[16 * D];  // split-K partials (aliased 4x1024 for w1)
    __shared__ float red[32];

    const int tid = threadIdx.x;
    const int b   = blockIdx.x;

    // D x D matvec roles: 4 cols per thread, 16 row-groups of 16 rows
    const int c4  = tid & 63;          // float4 column group: cols 4*c4..4*c4+3
    const int rg  = tid >> 6;          // row group 0..15
    // D x F matvec roles (w1): 4 cols per thread, 4 row-groups of 64 rows
    const int c4w = tid & 255;
    const int rgw = tid >> 8;          // 0..3

    // h0 = emb_tok[x[b,0]] + emb_pos[0]  (held by threads tid < 256)
    float hv = 0.0f;
    if (tid < D) {
        const int tok = xx[b * N];
        hv = emb_tok[tok * D + tid] + emb_pos[tid];
    }

    for (int l = 0; l < NL; ++l) {
        // ---------- LN1 ----------
        float s  = blockReduceSum(hv, red);
        float sq = blockReduceSum(hv * hv, red);
        float mu  = s * (1.0f / D);
        float var = sq * (1.0f / D) - mu * mu;
        float inv = rsqrtf(var + 1e-5f);
        if (tid < D)
            sh_vec[tid] = (hv - mu) * inv * ln1_s[l * D + tid] + ln1_b[l * D + tid];
        __syncthreads();

        // ---------- v0 = LN1(h) @ wv[l]  (split-K: 16 rows/thread) ----------
        {
            const float4* W = (const float4*)(wv + (size_t)l * D * D) + c4;
            float4 a = make_float4(0.f, 0.f, 0.f, 0.f);
            const int d0 = rg * 16;
            #pragma unroll
            for (int i = 0; i < 16; ++i) {
                float yd = sh_vec[d0 + i];
                float4 w = W[(size_t)(d0 + i) * (D / 4)];
                a.x = fmaf(yd, w.x, a.x); a.y = fmaf(yd, w.y, a.y);
                a.z = fmaf(yd, w.z, a.z); a.w = fmaf(yd, w.w, a.w);
            }
            float4* P = (float4*)(partial + rg * D) + c4;
            *P = a;
        }
        __syncthreads();
        if (tid < D) {
            float acc = 0.0f;
            #pragma unroll
            for (int r = 0; r < 16; ++r) acc += partial[r * D + tid];
            sh_vec[tid] = acc;         // v0
        }
        __syncthreads();

        // ---------- o = v0 @ wo[l] + bo[l];  h += o ----------
        {
            const float4* W = (const float4*)(wo + (size_t)l * D * D) + c4;
            float4 a = make_float4(0.f, 0.f, 0.f, 0.f);
            const int d0 = rg * 16;
            #pragma unroll
            for (int i = 0; i < 16; ++i) {
                float yd = sh_vec[d0 + i];
                float4 w = W[(size_t)(d0 + i) * (D / 4)];
                a.x = fmaf(yd, w.x, a.x); a.y = fmaf(yd, w.y, a.y);
                a.z = fmaf(yd, w.z, a.z); a.w = fmaf(yd, w.w, a.w);
            }
            float4* P = (float4*)(partial + rg * D) + c4;
            *P = a;
        }
        __syncthreads();
        if (tid < D) {
            float acc = bo[l * D + tid];
            #pragma unroll
            for (int r = 0; r < 16; ++r) acc += partial[r * D + tid];
            hv += acc;
        }
        // barrier inside next blockReduceSum protects partial/sh_vec reuse

        // ---------- LN2 ----------
        s  = blockReduceSum(hv, red);
        sq = blockReduceSum(hv * hv, red);
        mu  = s * (1.0f / D);
        var = sq * (1.0f / D) - mu * mu;
        inv = rsqrtf(var + 1e-5f);
        if (tid < D)
            sh_vec[tid] = (hv - mu) * inv * ln2_s[l * D + tid] + ln2_b[l * D + tid];
        __syncthreads();

        // ---------- hidden = gelu(y @ w1[l] + b1[l])  (split-K: 64 rows/thread) ----------
        {
            const float4* W = (const float4*)(w1 + (size_t)l * D * F) + c4w;
            float4 a = make_float4(0.f, 0.f, 0.f, 0.f);
            const int d0 = rgw * 64;
            #pragma unroll 8
            for (int i = 0; i < 64; ++i) {
                float yd = sh_vec[d0 + i];
                float4 w = W[(size_t)(d0 + i) * (F / 4)];
                a.x = fmaf(yd, w.x, a.x); a.y = fmaf(yd, w.y, a.y);
                a.z = fmaf(yd, w.z, a.z); a.w = fmaf(yd, w.w, a.w);
            }
            float4* P = (float4*)(partial + rgw * F) + c4w;
            *P = a;
        }
        __syncthreads();
        {   // every thread owns one hidden element
            float acc = b1[l * F + tid];
            #pragma unroll
            for (int r = 0; r < 4; ++r) acc += partial[r * F + tid];
            float g = gelu_tanh(acc);
            __syncthreads();           // all partial reads done before sh_vec overwrite
            sh_vec[tid] = g;
        }
        __syncthreads();

        // ---------- h += hidden @ w2[l] + b2[l]  (split-K: 64 rows/thread) ----------
        {
            const float4* W = (const float4*)(w2 + (size_t)l * F * D) + c4;
            float4 a = make_float4(0.f, 0.f, 0.f, 0.f);
            const int d0 = rg * 64;
            #pragma unroll 8
            for (int i = 0; i < 64; ++i) {
                float yd = sh_vec[d0 + i];
                float4 w = W[(size_t)(d0 + i) * (D / 4)];
                a.x = fmaf(yd, w.x, a.x); a.y = fmaf(yd, w.y, a.y);
                a.z = fmaf(yd, w.z, a.z); a.w = fmaf(yd, w.w, a.w);
            }
            float4* P = (float4*)(partial + rg * D) + c4;
            *P = a;
        }
        __syncthreads();
        if (tid < D) {
            float acc = b2[l * D + tid];
            #pragma unroll
            for (int r = 0; r < 16; ++r) acc += partial[r * D + tid];
            hv += acc;
        }
        // next LN1's reduction barrier protects reuse
    }

    // ---------- classifier: out[b] = h0 @ wcls + bcls ----------
    __syncthreads();
    if (tid < D) sh_vec[tid] = hv;
    __syncthreads();
    if (tid < NC) {
        float acc = bcls[tid];
        #pragma unroll 8
        for (int d = 0; d < D; ++d) acc = fmaf(sh_vec[d], wcls[d * NC + tid], acc);
        out[b * NC + tid] = acc;
    }
}

extern "C" void kernel_launch(void* const* d_in, const int* in_sizes, int n_in,
                              void* d_out, int out_size)
{
    const int*   xx      = (const int*)  d_in[0];
    const float* emb_tok = (const float*)d_in[1];
    const float* emb_pos = (const float*)d_in[2];
    const float* ln1_s   = (const float*)d_in[4];
    const float* ln1_b   = (const float*)d_in[5];
    const float* wv      = (const float*)d_in[8];
    const float* wo      = (const float*)d_in[9];
    const float* bo      = (const float*)d_in[10];
    const float* ln2_s   = (const float*)d_in[11];
    const float* ln2_b   = (const float*)d_in[12];
    const float* w1      = (const float*)d_in[13];
    const float* b1      = (const float*)d_in[14];
    const float* w2      = (const float*)d_in[15];
    const float* b2      = (const float*)d_in[16];
    const float* wcls    = (const float*)d_in[17];
    const float* bcls    = (const float*)d_in[18];
    float* out = (float*)d_out;

    const int B = out_size / NC;      // 16
    const int N = in_sizes[0] / B;    // 4096

    performer_cls_kernel<<<B, T>>>(xx, emb_tok, emb_pos, ln1_s, ln1_b,
                                   wv, wo, bo, ln2_s, ln2_b,
                                   w1, b1, w2, b2, wcls, bcls, out, N);
}